// round 16
// baseline (speedup 1.0000x reference)
#include <cuda_runtime.h>
#include <cuda_bf16.h>
#include <cuda_fp16.h>
#include <math.h>
#include <stdint.h>

#define BATCH 256
#define DIM   512
#define LW    32
#define PIX   196
#define TT    8
#define MBIG  (BATCH*PIX)   // 50176
#define BD    (BATCH*DIM)

// ---------------- scratch (static __device__ — allocation-guard safe) ----------------
__device__ __half g_kT [MBIG*512];
__device__ __half g_I2 [MBIG*512];
__device__ __half g_J2 [MBIG*512];
__device__ __half g_ra [MBIG*512];
__device__ __half g_Wk2 [DIM*DIM];
__device__ __half g_WI2 [DIM*2*DIM];
__device__ __half g_Wra2[DIM*DIM];
__device__ float g_cq  [BD];
__device__ float g_mI  [BD];
__device__ float g_r   [BD];
__device__ float g_msa [BD];
__device__ float g_tmp [BD];
__device__ float g_gate[BATCH];
__device__ float g_part [4*BD];   // split-K partials for m_prev
__device__ float g_part2[2*BD];   // split-K partials for m_

// ---------------- streams + events (created at load, pre-capture) ----
static cudaStream_t g_s2 = nullptr;
static cudaEvent_t g_evFork, g_evA, g_evB, g_evC, g_evG;
static struct StreamInit {
    StreamInit() {
        cudaStreamCreateWithFlags(&g_s2, cudaStreamNonBlocking);
        cudaEventCreateWithFlags(&g_evFork, cudaEventDisableTiming);
        cudaEventCreateWithFlags(&g_evA, cudaEventDisableTiming);
        cudaEventCreateWithFlags(&g_evB, cudaEventDisableTiming);
        cudaEventCreateWithFlags(&g_evC, cudaEventDisableTiming);
        cudaEventCreateWithFlags(&g_evG, cudaEventDisableTiming);
    }
} g_streamInit;

// ================= helpers =================
__device__ __forceinline__ uint32_t smem_u32(const void* p) {
    uint32_t a;
    asm("{ .reg .u64 t; cvta.to.shared.u64 t, %1; cvt.u32.u64 %0, t; }" : "=r"(a) : "l"(p));
    return a;
}
__device__ __forceinline__ void cpasync16(uint32_t dst, const void* src) {
    asm volatile("cp.async.cg.shared.global [%0], [%1], 16;" :: "r"(dst), "l"(src) : "memory");
}
__device__ __forceinline__ void cp_commit() { asm volatile("cp.async.commit_group;" ::: "memory"); }
__device__ __forceinline__ void cp_wait1() { asm volatile("cp.async.wait_group 1;" ::: "memory"); }
__device__ __forceinline__ void cp_wait0() { asm volatile("cp.async.wait_group 0;" ::: "memory"); }

__device__ __forceinline__ void ldm_x4(uint32_t& r0, uint32_t& r1, uint32_t& r2, uint32_t& r3, uint32_t a) {
    asm volatile("ldmatrix.sync.aligned.m8n8.x4.shared.b16 {%0,%1,%2,%3}, [%4];"
                 : "=r"(r0), "=r"(r1), "=r"(r2), "=r"(r3) : "r"(a));
}
__device__ __forceinline__ void mma16816h(float* c, const uint32_t* a, const uint32_t* b) {
    asm volatile("mma.sync.aligned.m16n8k16.row.col.f32.f16.f16.f32 "
                 "{%0,%1,%2,%3}, {%4,%5,%6,%7}, {%8,%9}, {%0,%1,%2,%3};"
                 : "+f"(c[0]), "+f"(c[1]), "+f"(c[2]), "+f"(c[3])
                 : "r"(a[0]), "r"(a[1]), "r"(a[2]), "r"(a[3]), "r"(b[0]), "r"(b[1]));
}

// ================= HMMA pure-fp16 GEMM v5: 256x128 CTA tile, 512 thr, 16 warps =================
// Warp grid 4x4 (wm 4 x 64 rows, wn 4 x 32 cols); warp tile 64x32 (inner loop as v4).
// Per SM/iter: tensor 2048 cyc vs LDSM+STS ~1875 -> tensor-bound.
// Stage = A 32KB + B 16KB = 48KB; 3-stage ring (144KB), 1 CTA/SM.
#define MG_STAGE 49152
#define MG_SMEM  (3*MG_STAGE)

template<int K, bool CONCAT, int EPI>
__global__ void __launch_bounds__(512, 1) mma_gemm(
    const __half* __restrict__ A0, const __half* __restrict__ A1,
    const __half* __restrict__ W,
    const float* __restrict__ bias, const float* __restrict__ scale,
    __half* __restrict__ O)
{
    constexpr int KIT = K / 64;
    extern __shared__ __align__(128) char dsm[];
    const uint32_t smb = smem_u32(dsm);

    const int tid = threadIdx.x, lane = tid & 31, wid = tid >> 5;
    const int bm = blockIdx.y * 256, bn = blockIdx.x * 128;
    const int wm = (wid >> 2) * 64, wn = (wid & 3) * 32;

    float acc[4][4][4];
    #pragma unroll
    for (int i = 0; i < 4; i++)
        #pragma unroll
        for (int j = 0; j < 4; j++)
            #pragma unroll
            for (int v = 0; v < 4; v++) acc[i][j][v] = 0.f;

    auto load_stage = [&](int it, int stage) {
        uint32_t sb = smb + (uint32_t)stage * MG_STAGE;
        int k0 = it * 64;
        const __half* Asrc = A0;
        int ac = k0;
        if (CONCAT && k0 >= 512) { Asrc = A1; ac = k0 - 512; }
        #pragma unroll
        for (int j = 0; j < 4; j++) {                 // A: 256 rows x 128B = 2048 chunks
            int f = tid + j * 512;
            int row = f >> 3, cc = f & 7;
            uint32_t d = sb + row * 128 + (uint32_t)((cc ^ (row & 7)) * 16);
            cpasync16(d, Asrc + (size_t)(bm + row) * 512 + ac + cc * 8);
        }
        #pragma unroll
        for (int j = 0; j < 2; j++) {                 // B: 128 rows x 128B = 1024 chunks
            int f = tid + j * 512;
            int row = f >> 3, cc = f & 7;
            uint32_t d = sb + 32768u + row * 128 + (uint32_t)((cc ^ (row & 7)) * 16);
            cpasync16(d, W + (size_t)(bn + row) * K + k0 + cc * 8);
        }
    };

    load_stage(0, 0); cp_commit();
    if (KIT > 1) { load_stage(1, 1); cp_commit(); }

    for (int it = 0; it < KIT; ++it) {
        if (it + 1 < KIT) cp_wait1(); else cp_wait0();
        __syncthreads();
        if (it + 2 < KIT) { load_stage(it + 2, (it + 2) % 3); cp_commit(); }

        const uint32_t sb = smb + (uint32_t)(it % 3) * MG_STAGE;
        const uint32_t sA = sb, sB = sb + 32768u;
        #pragma unroll
        for (int kp = 0; kp < 4; kp++) {
            uint32_t bf[2][4];
            #pragma unroll
            for (int pr = 0; pr < 2; pr++) {
                int nrow = wn + pr * 16 + ((lane >> 4) << 3) + (lane & 7);
                int chunk = (kp * 2 + ((lane >> 3) & 1)) ^ (nrow & 7);
                ldm_x4(bf[pr][0], bf[pr][1], bf[pr][2], bf[pr][3], sB + nrow * 128 + chunk * 16);
            }
            #pragma unroll
            for (int mi = 0; mi < 4; mi++) {
                uint32_t ah[4];
                int row = wm + mi * 16 + (lane & 15);
                int chunk = (kp * 2 + (lane >> 4)) ^ (row & 7);
                ldm_x4(ah[0], ah[1], ah[2], ah[3], sA + row * 128 + chunk * 16);
                #pragma unroll
                for (int ni = 0; ni < 4; ni++)
                    mma16816h(acc[mi][ni], ah, &bf[ni >> 1][(ni & 1) * 2]);
            }
        }
    }

    #pragma unroll
    for (int ni = 0; ni < 4; ni++) {
        const int n0 = bn + wn + ni * 8 + 2 * (lane & 3);
        const float b0 = bias[n0], b1 = bias[n0 + 1];
        #pragma unroll
        for (int mi = 0; mi < 4; mi++) {
            const int r0 = bm + wm + mi * 16 + (lane >> 2);
            const int r1 = r0 + 8;
            float* c = acc[mi][ni];
            if (EPI == 0) {
                const float* s0 = scale + (size_t)(r0 / PIX) * DIM;
                const float* s1 = scale + (size_t)(r1 / PIX) * DIM;
                float v00 = (c[0] + b0) * s0[n0], v01 = (c[1] + b1) * s0[n0 + 1];
                float v10 = (c[2] + b0) * s1[n0], v11 = (c[3] + b1) * s1[n0 + 1];
                *reinterpret_cast<__half2*>(O + (size_t)r0 * 512 + n0) = __floats2half2_rn(v00, v01);
                *reinterpret_cast<__half2*>(O + (size_t)r1 * 512 + n0) = __floats2half2_rn(v10, v11);
            } else {
                *reinterpret_cast<__half2*>(O + (size_t)r0 * 512 + n0) = __floats2half2_rn(c[0] + b0, c[1] + b1);
                *reinterpret_cast<__half2*>(O + (size_t)r1 * 512 + n0) = __floats2half2_rn(c[2] + b0, c[3] + b1);
            }
        }
    }
}

// ================= small fp32 GEMM: BM=BN=32, TM=TN=2, 128 CTAs =================
template<int K, bool CONCAT>
__global__ void __launch_bounds__(256) gemm_small(
    const float* __restrict__ A0, const float* __restrict__ A1,
    const float* __restrict__ W, const float* __restrict__ bias,
    float* __restrict__ C)
{
    constexpr int BM = 32, BN = 32, BK = 32;
    constexpr int NIT = K / BK;
    constexpr int halfK = K / 2;
    __shared__ __align__(16) float As[2][BK][32];
    __shared__ __align__(16) float Bs[2][BK][32];

    const int tid = threadIdx.x;
    const int bm = blockIdx.y * BM, bn = blockIdx.x * BN;
    const int tx = tid & 15, ty = tid >> 4;

    float4 pa, pb;
    auto gload = [&](int it) {
        int k0 = it * BK;
        int r = tid >> 3, c4 = (tid & 7) * 4;
        int gk = k0 + c4;
        const float* srcA;
        if (CONCAT) {
            srcA = (gk < halfK) ? (A0 + (size_t)(bm + r) * halfK + gk)
                                : (A1 + (size_t)(bm + r) * halfK + (gk - halfK));
        } else {
            srcA = A0 + (size_t)(bm + r) * K + gk;
        }
        pa = *reinterpret_cast<const float4*>(srcA);
        pb = *reinterpret_cast<const float4*>(W + (size_t)(bn + r) * K + gk);
    };
    auto sstore = [&](int buf) {
        int r = tid >> 3, c4 = (tid & 7) * 4;
        As[buf][c4 + 0][r] = pa.x; As[buf][c4 + 1][r] = pa.y;
        As[buf][c4 + 2][r] = pa.z; As[buf][c4 + 3][r] = pa.w;
        Bs[buf][c4 + 0][r] = pb.x; Bs[buf][c4 + 1][r] = pb.y;
        Bs[buf][c4 + 2][r] = pb.z; Bs[buf][c4 + 3][r] = pb.w;
    };

    float acc[2][2] = {{0.f, 0.f}, {0.f, 0.f}};

    gload(0); sstore(0); __syncthreads();
    for (int it = 0; it < NIT; ++it) {
        if (it + 1 < NIT) gload(it + 1);
        const int buf = it & 1;
        #pragma unroll
        for (int kk = 0; kk < BK; kk++) {
            float2 a = *reinterpret_cast<const float2*>(&As[buf][kk][ty * 2]);
            float2 b = *reinterpret_cast<const float2*>(&Bs[buf][kk][tx * 2]);
            acc[0][0] = fmaf(a.x, b.x, acc[0][0]); acc[0][1] = fmaf(a.x, b.y, acc[0][1]);
            acc[1][0] = fmaf(a.y, b.x, acc[1][0]); acc[1][1] = fmaf(a.y, b.y, acc[1][1]);
        }
        if (it + 1 < NIT) sstore(buf ^ 1);
        __syncthreads();
    }

    float b0 = bias ? bias[bn + tx * 2]     : 0.f;
    float b1 = bias ? bias[bn + tx * 2 + 1] : 0.f;
    #pragma unroll
    for (int i = 0; i < 2; i++) {
        int gm = bm + ty * 2 + i;
        float2 v = make_float2(acc[i][0] + b0, acc[i][1] + b1);
        *reinterpret_cast<float2*>(&C[(size_t)gm * DIM + bn + tx * 2]) = v;
    }
}

// ================= split-K partial GEMM (KCH=256 per z-chunk, no bias) =================
__global__ void __launch_bounds__(256) gemm_part(
    const float* __restrict__ A, int lda,
    const float* __restrict__ W, int ldw, int kw_off,
    float* __restrict__ part)
{
    constexpr int BK = 32, NIT = 8;   // KCH = 256
    __shared__ __align__(16) float As[2][BK][32];
    __shared__ __align__(16) float Bs[2][BK][32];

    const int tid = threadIdx.x;
    const int bm = blockIdx.y * 32, bn = blockIdx.x * 32;
    const int z = blockIdx.z;
    const int tx = tid & 15, ty = tid >> 4;
    const float* Az = A + z * 256;
    const float* Wz = W + kw_off + z * 256;
    float* Cz = part + (size_t)z * BD;

    float4 pa, pb;
    auto gload = [&](int it) {
        int k0 = it * BK;
        int r = tid >> 3, c4 = (tid & 7) * 4;
        int gk = k0 + c4;
        pa = *reinterpret_cast<const float4*>(Az + (size_t)(bm + r) * lda + gk);
        pb = *reinterpret_cast<const float4*>(Wz + (size_t)(bn + r) * ldw + gk);
    };
    auto sstore = [&](int buf) {
        int r = tid >> 3, c4 = (tid & 7) * 4;
        As[buf][c4 + 0][r] = pa.x; As[buf][c4 + 1][r] = pa.y;
        As[buf][c4 + 2][r] = pa.z; As[buf][c4 + 3][r] = pa.w;
        Bs[buf][c4 + 0][r] = pb.x; Bs[buf][c4 + 1][r] = pb.y;
        Bs[buf][c4 + 2][r] = pb.z; Bs[buf][c4 + 3][r] = pb.w;
    };

    float acc[2][2] = {{0.f, 0.f}, {0.f, 0.f}};
    gload(0); sstore(0); __syncthreads();
    for (int it = 0; it < NIT; ++it) {
        if (it + 1 < NIT) gload(it + 1);
        const int buf = it & 1;
        #pragma unroll
        for (int kk = 0; kk < BK; kk++) {
            float2 a = *reinterpret_cast<const float2*>(&As[buf][kk][ty * 2]);
            float2 b = *reinterpret_cast<const float2*>(&Bs[buf][kk][tx * 2]);
            acc[0][0] = fmaf(a.x, b.x, acc[0][0]); acc[0][1] = fmaf(a.x, b.y, acc[0][1]);
            acc[1][0] = fmaf(a.y, b.x, acc[1][0]); acc[1][1] = fmaf(a.y, b.y, acc[1][1]);
        }
        if (it + 1 < NIT) sstore(buf ^ 1);
        __syncthreads();
    }
    #pragma unroll
    for (int i = 0; i < 2; i++) {
        int gm = bm + ty * 2 + i;
        float2 v = make_float2(acc[i][0], acc[i][1]);
        *reinterpret_cast<float2*>(&Cz[(size_t)gm * DIM + bn + tx * 2]) = v;
    }
}

// ====== split-K partial GEMM with fused A = bias + (p0+p1)+(p2+p3) (m_prev on the fly) ======
__global__ void __launch_bounds__(256) gemm_part_fused(
    const float* __restrict__ parts,   // [4][BD], row stride 512
    const float* __restrict__ abias,   // bm_w
    const float* __restrict__ W, int ldw,
    float* __restrict__ part2)
{
    constexpr int BK = 32, NIT = 8;   // KCH = 256
    __shared__ __align__(16) float As[2][BK][32];
    __shared__ __align__(16) float Bs[2][BK][32];

    const int tid = threadIdx.x;
    const int bm = blockIdx.y * 32, bn = blockIdx.x * 32;
    const int z = blockIdx.z;
    const int tx = tid & 15, ty = tid >> 4;
    float* Cz = part2 + (size_t)z * BD;

    float4 pa, pb;
    auto gload = [&](int it) {
        int k0 = it * BK;
        int r = tid >> 3, c4 = (tid & 7) * 4;
        int gk = z * 256 + k0 + c4;
        size_t off = (size_t)(bm + r) * 512 + gk;
        float4 b4 = *reinterpret_cast<const float4*>(abias + gk);
        float4 x0 = *reinterpret_cast<const float4*>(parts + off);
        float4 x1 = *reinterpret_cast<const float4*>(parts + BD + off);
        float4 x2 = *reinterpret_cast<const float4*>(parts + 2 * (size_t)BD + off);
        float4 x3 = *reinterpret_cast<const float4*>(parts + 3 * (size_t)BD + off);
        pa.x = b4.x + ((x0.x + x1.x) + (x2.x + x3.x));
        pa.y = b4.y + ((x0.y + x1.y) + (x2.y + x3.y));
        pa.z = b4.z + ((x0.z + x1.z) + (x2.z + x3.z));
        pa.w = b4.w + ((x0.w + x1.w) + (x2.w + x3.w));
        pb = *reinterpret_cast<const float4*>(W + (size_t)(bn + r) * ldw + gk);
    };
    auto sstore = [&](int buf) {
        int r = tid >> 3, c4 = (tid & 7) * 4;
        As[buf][c4 + 0][r] = pa.x; As[buf][c4 + 1][r] = pa.y;
        As[buf][c4 + 2][r] = pa.z; As[buf][c4 + 3][r] = pa.w;
        Bs[buf][c4 + 0][r] = pb.x; Bs[buf][c4 + 1][r] = pb.y;
        Bs[buf][c4 + 2][r] = pb.z; Bs[buf][c4 + 3][r] = pb.w;
    };

    float acc[2][2] = {{0.f, 0.f}, {0.f, 0.f}};
    gload(0); sstore(0); __syncthreads();
    for (int it = 0; it < NIT; ++it) {
        if (it + 1 < NIT) gload(it + 1);
        const int buf = it & 1;
        #pragma unroll
        for (int kk = 0; kk < BK; kk++) {
            float2 a = *reinterpret_cast<const float2*>(&As[buf][kk][ty * 2]);
            float2 b = *reinterpret_cast<const float2*>(&Bs[buf][kk][tx * 2]);
            acc[0][0] = fmaf(a.x, b.x, acc[0][0]); acc[0][1] = fmaf(a.x, b.y, acc[0][1]);
            acc[1][0] = fmaf(a.y, b.x, acc[1][0]); acc[1][1] = fmaf(a.y, b.y, acc[1][1]);
        }
        if (it + 1 < NIT) sstore(buf ^ 1);
        __syncthreads();
    }
    #pragma unroll
    for (int i = 0; i < 2; i++) {
        int gm = bm + ty * 2 + i;
        float2 v = make_float2(acc[i][0], acc[i][1]);
        *reinterpret_cast<float2*>(&Cz[(size_t)gm * DIM + bn + tx * 2]) = v;
    }
}

// ---------------- fused reduce2 + final: m_new = g*m + (1-g)*((bm2 + p0 + p1) + tmp) ----------------
__global__ void final2_kernel(const float* __restrict__ part2, const float* __restrict__ bias2,
                              const float* __restrict__ m, const float* __restrict__ tmp,
                              const float* __restrict__ gate, float* __restrict__ mnew)
{
    int i = blockIdx.x * 256 + threadIdx.x;
    int b = i >> 9;
    float g = gate[b];
    float mm = bias2[i & 511] + part2[i] + part2[BD + i];
    mnew[i] = g * m[i] + (1.f - g) * (mm + tmp[i]);
}

// ================= conversions =================
__global__ void halve_w3_kernel(const float* __restrict__ wk, const float* __restrict__ wi,
                                const float* __restrict__ wra,
                                __half* __restrict__ ok, __half* __restrict__ oi,
                                __half* __restrict__ ora)
{
    int i = blockIdx.x * 256 + threadIdx.x;
    if (i < 262144) ok[i] = __float2half_rn(wk[i]);
    else if (i < 786432) { int j = i - 262144; oi[j] = __float2half_rn(wi[j]); }
    else { int j = i - 786432; ora[j] = __float2half_rn(wra[j]); }
}

__global__ void transpose_half_k(const float* __restrict__ k, __half* __restrict__ kT)
{
    __shared__ float tile[32][33];
    int b  = blockIdx.z;
    int p0 = blockIdx.x * 32;
    int c0 = blockIdx.y * 32;
    int tx = threadIdx.x, ty = threadIdx.y;
    #pragma unroll
    for (int j = 0; j < 32; j += 8) {
        int c = c0 + ty + j, p = p0 + tx;
        if (p < PIX) tile[ty + j][tx] = k[((size_t)b * DIM + c) * PIX + p];
    }
    __syncthreads();
    #pragma unroll
    for (int j = 0; j < 32; j += 8) {
        int p = p0 + ty + j, c = c0 + tx;
        if (p < PIX)
            kT[((size_t)b * PIX + p) * 512 + c] = __float2half_rn(tile[tx][ty + j]);
    }
}

// ---------------- reduction helpers ----------------
template<int NW>
__device__ __forceinline__ float blkSum(float v, float* red) {
    #pragma unroll
    for (int o = 16; o > 0; o >>= 1) v += __shfl_xor_sync(0xffffffffu, v, o);
    __syncthreads();
    if ((threadIdx.x & 31) == 0) red[threadIdx.x >> 5] = v;
    __syncthreads();
    float s = 0.f;
    #pragma unroll
    for (int i = 0; i < NW; i++) s += red[i];
    return s;
}

// ---------------- ControlUnit tail: warp-per-l ----------------
__global__ void __launch_bounds__(512) control_kernel(
    const float* __restrict__ cq, const float* __restrict__ cw,
    const int* __restrict__ mask, const float* __restrict__ Wca,
    const float* __restrict__ bca,
    float* __restrict__ cv_out, float* __restrict__ cnew)
{
    int b = blockIdx.x, tid = threadIdx.x;
    int w = tid >> 5, lane = tid & 31;
    __shared__ float u[DIM];
    __shared__ float s[LW];
    const float* cwb = cw + (size_t)b * LW * DIM;
    u[tid] = cq[(size_t)b * DIM + tid] * Wca[tid];
    __syncthreads();
    #pragma unroll
    for (int li = 0; li < 2; li++) {
        int l = w * 2 + li;
        const float* row = cwb + (size_t)l * DIM;
        float p = 0.f;
        #pragma unroll
        for (int j = 0; j < 16; j++) p = fmaf(u[lane + j * 32], row[lane + j * 32], p);
        #pragma unroll
        for (int o = 16; o > 0; o >>= 1) p += __shfl_xor_sync(0xffffffffu, p, o);
        if (lane == 0) s[l] = (mask[b * LW + l] > 0) ? (p + bca[0]) : -INFINITY;
    }
    __syncthreads();
    if (tid == 0) {
        float mx = -INFINITY;
        for (int l = 0; l < LW; l++) mx = fmaxf(mx, s[l]);
        float sm = 0.f;
        for (int l = 0; l < LW; l++) { float e = __expf(s[l] - mx); s[l] = e; sm += e; }
        float inv = 1.f / sm;
        for (int l = 0; l < LW; l++) { s[l] *= inv; cv_out[b * LW + l] = s[l]; }
    }
    __syncthreads();
    float a = 0.f;
    #pragma unroll
    for (int l = 0; l < LW; l++) a = fmaf(s[l], cwb[(size_t)l * DIM + tid], a);
    cnew[(size_t)b * DIM + tid] = a;
}

// ---------------- softmax over channels: warp-per-pixel, 28-pixel staging ----------
#define SMRV_TILE_STRIDE 517
#define SMRV_SMEM (28*SMRV_TILE_STRIDE*4)

__global__ void __launch_bounds__(512) softmax_rv_kernel(
    const __half* __restrict__ ra, const __half* __restrict__ kT,
    float* __restrict__ rv_out, float* __restrict__ r_out)
{
    extern __shared__ float tile[];
    __shared__ float rsum[DIM];
    const int b = blockIdx.x, tid = threadIdx.x;
    const int w = tid >> 5, lane = tid & 31;
    const __half* rab = ra + (size_t)b * PIX * 512;
    const __half* kb = kT + (size_t)b * PIX * 512;
    float* rvb = rv_out + (size_t)b * DIM * PIX;

    if (tid < DIM) rsum[tid] = 0.f;
    float racc[16];
    #pragma unroll
    for (int j = 0; j < 16; j++) racc[j] = 0.f;
    __syncthreads();

    for (int pp = 0; pp < 7; pp++) {
        if (w < 14) {
            #pragma unroll
            for (int half = 0; half < 2; half++) {
                const int i = half * 14 + w;
                const int p = pp * 28 + i;
                float x[16];
                #pragma unroll
                for (int q = 0; q < 4; q++) {
                    const size_t ridx = (size_t)p * 512 + q * 128 + lane * 4;
                    __half2 r0 = *reinterpret_cast<const __half2*>(rab + ridx);
                    __half2 r1 = *reinterpret_cast<const __half2*>(rab + ridx + 2);
                    x[q * 4 + 0] = __half2float(r0.x); x[q * 4 + 1] = __half2float(r0.y);
                    x[q * 4 + 2] = __half2float(r1.x); x[q * 4 + 3] = __half2float(r1.y);
                }
                float mx = x[0];
                #pragma unroll
                for (int j = 1; j < 16; j++) mx = fmaxf(mx, x[j]);
                #pragma unroll
                for (int o = 16; o > 0; o >>= 1) mx = fmaxf(mx, __shfl_xor_sync(0xffffffffu, mx, o));
                float sm = 0.f;
                #pragma unroll
                for (int j = 0; j < 16; j++) { x[j] = __expf(x[j] - mx); sm += x[j]; }
                #pragma unroll
                for (int o = 16; o > 0; o >>= 1) sm += __shfl_xor_sync(0xffffffffu, sm, o);
                const float inv = 1.f / sm;
                #pragma unroll
                for (int q = 0; q < 4; q++) {
                    float rv0 = x[q * 4 + 0] * inv, rv1 = x[q * 4 + 1] * inv;
                    float rv2 = x[q * 4 + 2] * inv, rv3 = x[q * 4 + 3] * inv;
                    float* tr = &tile[i * SMRV_TILE_STRIDE + q * 128 + lane * 4];
                    tr[0] = rv0; tr[1] = rv1; tr[2] = rv2; tr[3] = rv3;
                    const size_t kidx = (size_t)p * 512 + q * 128 + lane * 4;
                    __half2 kh0 = *reinterpret_cast<const __half2*>(kb + kidx);
                    __half2 kh1 = *reinterpret_cast<const __half2*>(kb + kidx + 2);
                    racc[q * 4 + 0] = fmaf(rv0, __half2float(kh0.x), racc[q * 4 + 0]);
                    racc[q * 4 + 1] = fmaf(rv1, __half2float(kh0.y), racc[q * 4 + 1]);
                    racc[q * 4 + 2] = fmaf(rv2, __half2float(kh1.x), racc[q * 4 + 2]);
                    racc[q * 4 + 3] = fmaf(rv3, __half2float(kh1.y), racc[q * 4 + 3]);
                }
            }
        }
        __syncthreads();
        #pragma unroll 1
        for (int cc = 0; cc < 32; cc++) {
            int c = w * 32 + cc;
            if (lane < 28) rvb[(size_t)c * PIX + pp * 28 + lane] = tile[lane * SMRV_TILE_STRIDE + c];
        }
        __syncthreads();
    }

    #pragma unroll
    for (int q = 0; q < 4; q++)
        #pragma unroll
        for (int j = 0; j < 4; j++)
            atomicAdd(&rsum[q * 128 + lane * 4 + j], racc[q * 4 + j]);
    __syncthreads();
    if (tid < DIM) r_out[(size_t)b * DIM + tid] = rsum[tid];
}

// ---------------- gate, sa softmax over T, m_sa ----------------
__global__ void gate_sa_kernel(const float* __restrict__ cnew, const float* __restrict__ Wc,
                               const float* __restrict__ bc,   const float* __restrict__ cs,
                               const float* __restrict__ Wsa,  const float* __restrict__ bsa,
                               const float* __restrict__ ms,
                               float* __restrict__ gate_out, float* __restrict__ msa_out)
{
    int b = blockIdx.x, tid = threadIdx.x;
    __shared__ float red[8];
    __shared__ float sa[TT];
    __shared__ float gsh;
    float p = 0.f;
    for (int d = tid; d < DIM; d += 256) p += cnew[(size_t)b * DIM + d] * Wc[d];
    float tot = blkSum<8>(p, red);
    if (tid == 0) gsh = 1.f / (1.f + __expf(-(tot + bc[0])));
    __syncthreads();
    float gate = gsh;
    for (int t8 = 0; t8 < TT; t8++) {
        float qv = 0.f;
        const float* csrow = cs + ((size_t)t8 * BATCH + b) * DIM;
        for (int d = tid; d < DIM; d += 256) qv += csrow[d] * Wsa[d];
        float qt = blkSum<8>(qv, red);
        if (tid == 0) sa[t8] = gate * qt + bsa[0];
    }
    __syncthreads();
    if (tid == 0) {
        float mx = -INFINITY;
        for (int i = 0; i < TT; i++) mx = fmaxf(mx, sa[i]);
        float sm = 0.f;
        for (int i = 0; i < TT; i++) { float e = __expf(sa[i] - mx); sa[i] = e; sm += e; }
        float inv = 1.f / sm;
        for (int i = 0; i < TT; i++) sa[i] *= inv;
    }
    __syncthreads();
    for (int d = tid; d < DIM; d += 256) {
        float a = 0.f;
        #pragma unroll
        for (int i = 0; i < TT; i++)
            a = fmaf(sa[i], ms[((size_t)i * BATCH + b) * DIM + d], a);
        msa_out[(size_t)b * DIM + d] = a;
    }
    if (tid == 0) gate_out[b] = gate;
}

// ---------------- launch ----------------
extern "C" void kernel_launch(void* const* d_in, const int* in_sizes, int n_in,
                              void* d_out, int out_size)
{
    const float* c    = (const float*)d_in[0];
    const float* m    = (const float*)d_in[1];
    const float* k    = (const float*)d_in[2];
    const float* q    = (const float*)d_in[3];
    const float* cw   = (const float*)d_in[4];
    const int*   mask = (const int*)  d_in[5];
    const float* cs   = (const float*)d_in[6];
    const float* ms   = (const float*)d_in[7];
    const float* Wcq  = (const float*)d_in[8];
    const float* bcq  = (const float*)d_in[9];
    const float* Wca  = (const float*)d_in[10];
    const float* bca  = (const float*)d_in[11];
    const float* Wm_r = (const float*)d_in[12];
    const float* bm_r = (const float*)d_in[13];
    const float* Wk   = (const float*)d_in[14];
    const float* bk   = (const float*)d_in[15];
    const float* WI   = (const float*)d_in[16];
    const float* bI   = (const float*)d_in[17];
    const float* Wra  = (const float*)d_in[18];
    const float* bra  = (const float*)d_in[19];
    const float* Wm_w = (const float*)d_in[20];
    const float* bm_w = (const float*)d_in[21];
    const float* Wsa  = (const float*)d_in[22];
    const float* bsa  = (const float*)d_in[23];
    const float* Wm2  = (const float*)d_in[24];
    const float* bm2  = (const float*)d_in[25];
    const float* Wc   = (const float*)d_in[26];
    const float* bc   = (const float*)d_in[27];
    const float* Ws   = (const float*)d_in[28];

    float* out      = (float*)d_out;
    float* out_cnew = out;
    float* out_mnew = out + 131072;
    float* out_cv   = out + 262144;
    float* out_rv   = out + 270336;

    __half *p_kT, *p_I2, *p_J2, *p_ra, *p_Wk2, *p_WI2, *p_Wra2;
    float *p_cq, *p_mI, *p_r, *p_msa, *p_tmp, *p_gate, *p_part, *p_part2;
    cudaGetSymbolAddress((void**)&p_kT,   g_kT);
    cudaGetSymbolAddress((void**)&p_I2,   g_I2);
    cudaGetSymbolAddress((void**)&p_J2,   g_J2);
    cudaGetSymbolAddress((void**)&p_ra,   g_ra);
    cudaGetSymbolAddress((void**)&p_Wk2,  g_Wk2);
    cudaGetSymbolAddress((void**)&p_WI2,  g_WI2);
    cudaGetSymbolAddress((void**)&p_Wra2, g_Wra2);
    cudaGetSymbolAddress((void**)&p_cq,   g_cq);
    cudaGetSymbolAddress((void**)&p_mI,   g_mI);
    cudaGetSymbolAddress((void**)&p_r,    g_r);
    cudaGetSymbolAddress((void**)&p_msa,  g_msa);
    cudaGetSymbolAddress((void**)&p_tmp,  g_tmp);
    cudaGetSymbolAddress((void**)&p_gate, g_gate);
    cudaGetSymbolAddress((void**)&p_part, g_part);
    cudaGetSymbolAddress((void**)&p_part2,g_part2);

    cudaFuncSetAttribute((const void*)mma_gemm<512,  false, 0>, cudaFuncAttributeMaxDynamicSharedMemorySize, MG_SMEM);
    cudaFuncSetAttribute((const void*)mma_gemm<1024, true,  0>, cudaFuncAttributeMaxDynamicSharedMemorySize, MG_SMEM);
    cudaFuncSetAttribute((const void*)mma_gemm<512,  false, 1>, cudaFuncAttributeMaxDynamicSharedMemorySize, MG_SMEM);
    cudaFuncSetAttribute(softmax_rv_kernel, cudaFuncAttributeMaxDynamicSharedMemorySize, SMRV_SMEM);

    // ================== two-stream DAG ==================
    cudaStream_t s2 = g_s2;

    cudaEventRecord(g_evFork, 0);
    cudaStreamWaitEvent(s2, g_evFork, 0);

    // s0: transpose
    transpose_half_k<<<dim3(7, 16, BATCH), dim3(32, 8)>>>(k, p_kT);

    // s2 chain (hidden under transpose + big GEMMs)
    halve_w3_kernel<<<4096, 256, 0, s2>>>(Wk, WI, Wra, p_Wk2, p_WI2, p_Wra2);
    gemm_small<512, false><<<dim3(16, 8), 256, 0, s2>>>(m, nullptr, Wm_r, bm_r, p_mI);
    cudaEventRecord(g_evA, s2);
    gemm_small<1024, true><<<dim3(16, 8), 256, 0, s2>>>(c, q, Wcq, bcq, p_cq);
    control_kernel<<<BATCH, 512, 0, s2>>>(p_cq, cw, mask, Wca, bca, out_cv, out_cnew);
    cudaEventRecord(g_evB, s2);
    gemm_part<<<dim3(16, 8, 2), 256, 0, s2>>>(m, 512, Wm_w, 1024, 512, p_part + 2 * BD);
    cudaEventRecord(g_evG, s2);
    gate_sa_kernel<<<BATCH, 256, 0, s2>>>(out_cnew, Wc, bc, cs, Wsa, bsa, ms, p_gate, p_msa);
    gemm_small<512, false><<<dim3(16, 8), 256, 0, s2>>>(p_msa, nullptr, Ws, nullptr, p_tmp);
    cudaEventRecord(g_evC, s2);

    // s0 chain (256-row tiles: grid y = 196)
    cudaStreamWaitEvent(0, g_evA, 0);
    mma_gemm<512, false, 0><<<dim3(4, 196), 512, MG_SMEM>>>(
        p_kT, nullptr, p_Wk2, bk, p_mI, p_I2);
    cudaStreamWaitEvent(0, g_evB, 0);
    mma_gemm<1024, true, 0><<<dim3(4, 196), 512, MG_SMEM>>>(
        p_I2, p_kT, p_WI2, bI, out_cnew, p_J2);
    mma_gemm<512, false, 1><<<dim3(4, 196), 512, MG_SMEM>>>(
        p_J2, nullptr, p_Wra2, bra, nullptr, p_ra);
    softmax_rv_kernel<<<BATCH, 512, SMRV_SMEM>>>(p_ra, p_kT, out_rv, p_r);
    gemm_part<<<dim3(16, 8, 2), 256>>>(p_r, 512, Wm_w, 1024, 0, p_part);
    cudaStreamWaitEvent(0, g_evG, 0);
    gemm_part_fused<<<dim3(16, 8, 2), 256>>>(p_part, bm_w, Wm2, 512, p_part2);
    cudaStreamWaitEvent(0, g_evC, 0);
    final2_kernel<<<BD / 256, 256>>>(p_part2, bm2, m, p_tmp, p_gate, out_mnew);
}

// round 17
// speedup vs baseline: 1.0697x; 1.0697x over previous
#include <cuda_runtime.h>
#include <cuda_bf16.h>
#include <cuda_fp16.h>
#include <math.h>
#include <stdint.h>

#define BATCH 256
#define DIM   512
#define LW    32
#define PIX   196
#define TT    8
#define MBIG  (BATCH*PIX)   // 50176
#define BD    (BATCH*DIM)

// ---------------- scratch (static __device__ — allocation-guard safe) ----------------
__device__ __half g_kT [MBIG*512];
__device__ __half g_I2 [MBIG*512];
__device__ __half g_J2 [MBIG*512];
__device__ __half g_ra [MBIG*512];
__device__ __half g_Wk2 [DIM*DIM];
__device__ __half g_WI2 [DIM*2*DIM];
__device__ __half g_Wra2[DIM*DIM];
__device__ float g_cq  [BD];
__device__ float g_mI  [BD];
__device__ float g_r   [BD];
__device__ float g_msa [BD];
__device__ float g_tmp [BD];
__device__ float g_gate[BATCH];
__device__ float g_part [4*BD];   // split-K partials for m_prev
__device__ float g_part2[2*BD];   // split-K partials for m_

// ---------------- streams + events (created at load, pre-capture) ----
static cudaStream_t g_s2 = nullptr;
static cudaEvent_t g_evFork, g_evA, g_evB, g_evC, g_evG;
static struct StreamInit {
    StreamInit() {
        cudaStreamCreateWithFlags(&g_s2, cudaStreamNonBlocking);
        cudaEventCreateWithFlags(&g_evFork, cudaEventDisableTiming);
        cudaEventCreateWithFlags(&g_evA, cudaEventDisableTiming);
        cudaEventCreateWithFlags(&g_evB, cudaEventDisableTiming);
        cudaEventCreateWithFlags(&g_evC, cudaEventDisableTiming);
        cudaEventCreateWithFlags(&g_evG, cudaEventDisableTiming);
    }
} g_streamInit;

// ================= helpers =================
__device__ __forceinline__ uint32_t smem_u32(const void* p) {
    uint32_t a;
    asm("{ .reg .u64 t; cvta.to.shared.u64 t, %1; cvt.u32.u64 %0, t; }" : "=r"(a) : "l"(p));
    return a;
}
__device__ __forceinline__ void cpasync16(uint32_t dst, const void* src) {
    asm volatile("cp.async.cg.shared.global [%0], [%1], 16;" :: "r"(dst), "l"(src) : "memory");
}
__device__ __forceinline__ void cp_commit() { asm volatile("cp.async.commit_group;" ::: "memory"); }
__device__ __forceinline__ void cp_wait1() { asm volatile("cp.async.wait_group 1;" ::: "memory"); }
__device__ __forceinline__ void cp_wait0() { asm volatile("cp.async.wait_group 0;" ::: "memory"); }

__device__ __forceinline__ void ldm_x4(uint32_t& r0, uint32_t& r1, uint32_t& r2, uint32_t& r3, uint32_t a) {
    asm volatile("ldmatrix.sync.aligned.m8n8.x4.shared.b16 {%0,%1,%2,%3}, [%4];"
                 : "=r"(r0), "=r"(r1), "=r"(r2), "=r"(r3) : "r"(a));
}
__device__ __forceinline__ void mma16816h(float* c, const uint32_t* a, const uint32_t* b) {
    asm volatile("mma.sync.aligned.m16n8k16.row.col.f32.f16.f16.f32 "
                 "{%0,%1,%2,%3}, {%4,%5,%6,%7}, {%8,%9}, {%0,%1,%2,%3};"
                 : "+f"(c[0]), "+f"(c[1]), "+f"(c[2]), "+f"(c[3])
                 : "r"(a[0]), "r"(a[1]), "r"(a[2]), "r"(a[3]), "r"(b[0]), "r"(b[1]));
}

// ================= HMMA pure-fp16 GEMM v4 (128x128, 2 CTAs/SM) =================
#define MG_STAGE 32768
#define MG_SMEM  (3*MG_STAGE)

template<int K, bool CONCAT, int EPI>
__global__ void __launch_bounds__(256, 2) mma_gemm(
    const __half* __restrict__ A0, const __half* __restrict__ A1,
    const __half* __restrict__ W,
    const float* __restrict__ bias, const float* __restrict__ scale,
    __half* __restrict__ O)
{
    constexpr int KIT = K / 64;
    extern __shared__ __align__(128) char dsm[];
    const uint32_t smb = smem_u32(dsm);

    const int tid = threadIdx.x, lane = tid & 31, wid = tid >> 5;
    const int bm = blockIdx.y * 128, bn = blockIdx.x * 128;
    const int wm = (wid >> 2) * 64, wn = (wid & 3) * 32;

    float acc[4][4][4];
    #pragma unroll
    for (int i = 0; i < 4; i++)
        #pragma unroll
        for (int j = 0; j < 4; j++)
            #pragma unroll
            for (int v = 0; v < 4; v++) acc[i][j][v] = 0.f;

    auto load_stage = [&](int it, int stage) {
        uint32_t sb = smb + (uint32_t)stage * MG_STAGE;
        int k0 = it * 64;
        const __half* Asrc = A0;
        int ac = k0;
        if (CONCAT && k0 >= 512) { Asrc = A1; ac = k0 - 512; }
        #pragma unroll
        for (int j = 0; j < 4; j++) {
            int f = tid + j * 256;
            int row = f >> 3, cc = f & 7;
            uint32_t d = sb + row * 128 + (uint32_t)((cc ^ (row & 7)) * 16);
            cpasync16(d, Asrc + (size_t)(bm + row) * 512 + ac + cc * 8);
            cpasync16(d + 16384u, W + (size_t)(bn + row) * K + k0 + cc * 8);
        }
    };

    load_stage(0, 0); cp_commit();
    if (KIT > 1) { load_stage(1, 1); cp_commit(); }

    for (int it = 0; it < KIT; ++it) {
        if (it + 1 < KIT) cp_wait1(); else cp_wait0();
        __syncthreads();
        if (it + 2 < KIT) { load_stage(it + 2, (it + 2) % 3); cp_commit(); }

        const uint32_t sb = smb + (uint32_t)(it % 3) * MG_STAGE;
        const uint32_t sA = sb, sB = sb + 16384u;
        #pragma unroll
        for (int kp = 0; kp < 4; kp++) {
            uint32_t bf[2][4];
            #pragma unroll
            for (int pr = 0; pr < 2; pr++) {
                int nrow = wn + pr * 16 + ((lane >> 4) << 3) + (lane & 7);
                int chunk = (kp * 2 + ((lane >> 3) & 1)) ^ (nrow & 7);
                ldm_x4(bf[pr][0], bf[pr][1], bf[pr][2], bf[pr][3], sB + nrow * 128 + chunk * 16);
            }
            #pragma unroll
            for (int mi = 0; mi < 4; mi++) {
                uint32_t ah[4];
                int row = wm + mi * 16 + (lane & 15);
                int chunk = (kp * 2 + (lane >> 4)) ^ (row & 7);
                ldm_x4(ah[0], ah[1], ah[2], ah[3], sA + row * 128 + chunk * 16);
                #pragma unroll
                for (int ni = 0; ni < 4; ni++)
                    mma16816h(acc[mi][ni], ah, &bf[ni >> 1][(ni & 1) * 2]);
            }
        }
    }

    #pragma unroll
    for (int ni = 0; ni < 4; ni++) {
        const int n0 = bn + wn + ni * 8 + 2 * (lane & 3);
        const float b0 = bias[n0], b1 = bias[n0 + 1];
        #pragma unroll
        for (int mi = 0; mi < 4; mi++) {
            const int r0 = bm + wm + mi * 16 + (lane >> 2);
            const int r1 = r0 + 8;
            float* c = acc[mi][ni];
            if (EPI == 0) {
                const float* s0 = scale + (size_t)(r0 / PIX) * DIM;
                const float* s1 = scale + (size_t)(r1 / PIX) * DIM;
                float v00 = (c[0] + b0) * s0[n0], v01 = (c[1] + b1) * s0[n0 + 1];
                float v10 = (c[2] + b0) * s1[n0], v11 = (c[3] + b1) * s1[n0 + 1];
                *reinterpret_cast<__half2*>(O + (size_t)r0 * 512 + n0) = __floats2half2_rn(v00, v01);
                *reinterpret_cast<__half2*>(O + (size_t)r1 * 512 + n0) = __floats2half2_rn(v10, v11);
            } else {
                *reinterpret_cast<__half2*>(O + (size_t)r0 * 512 + n0) = __floats2half2_rn(c[0] + b0, c[1] + b1);
                *reinterpret_cast<__half2*>(O + (size_t)r1 * 512 + n0) = __floats2half2_rn(c[2] + b0, c[3] + b1);
            }
        }
    }
}

// ================= small fp32 GEMM: BM=BN=32, TM=TN=2, 128 CTAs =================
template<int K, bool CONCAT>
__global__ void __launch_bounds__(256) gemm_small(
    const float* __restrict__ A0, const float* __restrict__ A1,
    const float* __restrict__ W, const float* __restrict__ bias,
    float* __restrict__ C)
{
    constexpr int BM = 32, BN = 32, BK = 32;
    constexpr int NIT = K / BK;
    constexpr int halfK = K / 2;
    __shared__ __align__(16) float As[2][BK][32];
    __shared__ __align__(16) float Bs[2][BK][32];

    const int tid = threadIdx.x;
    const int bm = blockIdx.y * BM, bn = blockIdx.x * BN;
    const int tx = tid & 15, ty = tid >> 4;

    float4 pa, pb;
    auto gload = [&](int it) {
        int k0 = it * BK;
        int r = tid >> 3, c4 = (tid & 7) * 4;
        int gk = k0 + c4;
        const float* srcA;
        if (CONCAT) {
            srcA = (gk < halfK) ? (A0 + (size_t)(bm + r) * halfK + gk)
                                : (A1 + (size_t)(bm + r) * halfK + (gk - halfK));
        } else {
            srcA = A0 + (size_t)(bm + r) * K + gk;
        }
        pa = *reinterpret_cast<const float4*>(srcA);
        pb = *reinterpret_cast<const float4*>(W + (size_t)(bn + r) * K + gk);
    };
    auto sstore = [&](int buf) {
        int r = tid >> 3, c4 = (tid & 7) * 4;
        As[buf][c4 + 0][r] = pa.x; As[buf][c4 + 1][r] = pa.y;
        As[buf][c4 + 2][r] = pa.z; As[buf][c4 + 3][r] = pa.w;
        Bs[buf][c4 + 0][r] = pb.x; Bs[buf][c4 + 1][r] = pb.y;
        Bs[buf][c4 + 2][r] = pb.z; Bs[buf][c4 + 3][r] = pb.w;
    };

    float acc[2][2] = {{0.f, 0.f}, {0.f, 0.f}};

    gload(0); sstore(0); __syncthreads();
    for (int it = 0; it < NIT; ++it) {
        if (it + 1 < NIT) gload(it + 1);
        const int buf = it & 1;
        #pragma unroll
        for (int kk = 0; kk < BK; kk++) {
            float2 a = *reinterpret_cast<const float2*>(&As[buf][kk][ty * 2]);
            float2 b = *reinterpret_cast<const float2*>(&Bs[buf][kk][tx * 2]);
            acc[0][0] = fmaf(a.x, b.x, acc[0][0]); acc[0][1] = fmaf(a.x, b.y, acc[0][1]);
            acc[1][0] = fmaf(a.y, b.x, acc[1][0]); acc[1][1] = fmaf(a.y, b.y, acc[1][1]);
        }
        if (it + 1 < NIT) sstore(buf ^ 1);
        __syncthreads();
    }

    float b0 = bias ? bias[bn + tx * 2]     : 0.f;
    float b1 = bias ? bias[bn + tx * 2 + 1] : 0.f;
    #pragma unroll
    for (int i = 0; i < 2; i++) {
        int gm = bm + ty * 2 + i;
        float2 v = make_float2(acc[i][0] + b0, acc[i][1] + b1);
        *reinterpret_cast<float2*>(&C[(size_t)gm * DIM + bn + tx * 2]) = v;
    }
}

// ================= split-K partial GEMM (KCH=256 per z-chunk, no bias) =================
__global__ void __launch_bounds__(256) gemm_part(
    const float* __restrict__ A, int lda,
    const float* __restrict__ W, int ldw, int kw_off,
    float* __restrict__ part)
{
    constexpr int BK = 32, NIT = 8;   // KCH = 256
    __shared__ __align__(16) float As[2][BK][32];
    __shared__ __align__(16) float Bs[2][BK][32];

    const int tid = threadIdx.x;
    const int bm = blockIdx.y * 32, bn = blockIdx.x * 32;
    const int z = blockIdx.z;
    const int tx = tid & 15, ty = tid >> 4;
    const float* Az = A + z * 256;
    const float* Wz = W + kw_off + z * 256;
    float* Cz = part + (size_t)z * BD;

    float4 pa, pb;
    auto gload = [&](int it) {
        int k0 = it * BK;
        int r = tid >> 3, c4 = (tid & 7) * 4;
        int gk = k0 + c4;
        pa = *reinterpret_cast<const float4*>(Az + (size_t)(bm + r) * lda + gk);
        pb = *reinterpret_cast<const float4*>(Wz + (size_t)(bn + r) * ldw + gk);
    };
    auto sstore = [&](int buf) {
        int r = tid >> 3, c4 = (tid & 7) * 4;
        As[buf][c4 + 0][r] = pa.x; As[buf][c4 + 1][r] = pa.y;
        As[buf][c4 + 2][r] = pa.z; As[buf][c4 + 3][r] = pa.w;
        Bs[buf][c4 + 0][r] = pb.x; Bs[buf][c4 + 1][r] = pb.y;
        Bs[buf][c4 + 2][r] = pb.z; Bs[buf][c4 + 3][r] = pb.w;
    };

    float acc[2][2] = {{0.f, 0.f}, {0.f, 0.f}};
    gload(0); sstore(0); __syncthreads();
    for (int it = 0; it < NIT; ++it) {
        if (it + 1 < NIT) gload(it + 1);
        const int buf = it & 1;
        #pragma unroll
        for (int kk = 0; kk < BK; kk++) {
            float2 a = *reinterpret_cast<const float2*>(&As[buf][kk][ty * 2]);
            float2 b = *reinterpret_cast<const float2*>(&Bs[buf][kk][tx * 2]);
            acc[0][0] = fmaf(a.x, b.x, acc[0][0]); acc[0][1] = fmaf(a.x, b.y, acc[0][1]);
            acc[1][0] = fmaf(a.y, b.x, acc[1][0]); acc[1][1] = fmaf(a.y, b.y, acc[1][1]);
        }
        if (it + 1 < NIT) sstore(buf ^ 1);
        __syncthreads();
    }
    #pragma unroll
    for (int i = 0; i < 2; i++) {
        int gm = bm + ty * 2 + i;
        float2 v = make_float2(acc[i][0], acc[i][1]);
        *reinterpret_cast<float2*>(&Cz[(size_t)gm * DIM + bn + tx * 2]) = v;
    }
}

// ====== split-K partial GEMM with fused A = bias + (p0+p1)+(p2+p3) (m_prev on the fly) ======
__global__ void __launch_bounds__(256) gemm_part_fused(
    const float* __restrict__ parts,   // [4][BD], row stride 512
    const float* __restrict__ abias,   // bm_w
    const float* __restrict__ W, int ldw,
    float* __restrict__ part2)
{
    constexpr int BK = 32, NIT = 8;   // KCH = 256
    __shared__ __align__(16) float As[2][BK][32];
    __shared__ __align__(16) float Bs[2][BK][32];

    const int tid = threadIdx.x;
    const int bm = blockIdx.y * 32, bn = blockIdx.x * 32;
    const int z = blockIdx.z;
    const int tx = tid & 15, ty = tid >> 4;
    float* Cz = part2 + (size_t)z * BD;

    float4 pa, pb;
    auto gload = [&](int it) {
        int k0 = it * BK;
        int r = tid >> 3, c4 = (tid & 7) * 4;
        int gk = z * 256 + k0 + c4;
        size_t off = (size_t)(bm + r) * 512 + gk;
        float4 b4 = *reinterpret_cast<const float4*>(abias + gk);
        float4 x0 = *reinterpret_cast<const float4*>(parts + off);
        float4 x1 = *reinterpret_cast<const float4*>(parts + BD + off);
        float4 x2 = *reinterpret_cast<const float4*>(parts + 2 * (size_t)BD + off);
        float4 x3 = *reinterpret_cast<const float4*>(parts + 3 * (size_t)BD + off);
        pa.x = b4.x + ((x0.x + x1.x) + (x2.x + x3.x));
        pa.y = b4.y + ((x0.y + x1.y) + (x2.y + x3.y));
        pa.z = b4.z + ((x0.z + x1.z) + (x2.z + x3.z));
        pa.w = b4.w + ((x0.w + x1.w) + (x2.w + x3.w));
        pb = *reinterpret_cast<const float4*>(W + (size_t)(bn + r) * ldw + gk);
    };
    auto sstore = [&](int buf) {
        int r = tid >> 3, c4 = (tid & 7) * 4;
        As[buf][c4 + 0][r] = pa.x; As[buf][c4 + 1][r] = pa.y;
        As[buf][c4 + 2][r] = pa.z; As[buf][c4 + 3][r] = pa.w;
        Bs[buf][c4 + 0][r] = pb.x; Bs[buf][c4 + 1][r] = pb.y;
        Bs[buf][c4 + 2][r] = pb.z; Bs[buf][c4 + 3][r] = pb.w;
    };

    float acc[2][2] = {{0.f, 0.f}, {0.f, 0.f}};
    gload(0); sstore(0); __syncthreads();
    for (int it = 0; it < NIT; ++it) {
        if (it + 1 < NIT) gload(it + 1);
        const int buf = it & 1;
        #pragma unroll
        for (int kk = 0; kk < BK; kk++) {
            float2 a = *reinterpret_cast<const float2*>(&As[buf][kk][ty * 2]);
            float2 b = *reinterpret_cast<const float2*>(&Bs[buf][kk][tx * 2]);
            acc[0][0] = fmaf(a.x, b.x, acc[0][0]); acc[0][1] = fmaf(a.x, b.y, acc[0][1]);
            acc[1][0] = fmaf(a.y, b.x, acc[1][0]); acc[1][1] = fmaf(a.y, b.y, acc[1][1]);
        }
        if (it + 1 < NIT) sstore(buf ^ 1);
        __syncthreads();
    }
    #pragma unroll
    for (int i = 0; i < 2; i++) {
        int gm = bm + ty * 2 + i;
        float2 v = make_float2(acc[i][0], acc[i][1]);
        *reinterpret_cast<float2*>(&Cz[(size_t)gm * DIM + bn + tx * 2]) = v;
    }
}

// ---------------- fused reduce2 + final: m_new = g*m + (1-g)*((bm2 + p0 + p1) + tmp) ----------------
__global__ void final2_kernel(const float* __restrict__ part2, const float* __restrict__ bias2,
                              const float* __restrict__ m, const float* __restrict__ tmp,
                              const float* __restrict__ gate, float* __restrict__ mnew)
{
    int i = blockIdx.x * 256 + threadIdx.x;
    int b = i >> 9;
    float g = gate[b];
    float mm = bias2[i & 511] + part2[i] + part2[BD + i];
    mnew[i] = g * m[i] + (1.f - g) * (mm + tmp[i]);
}

// ================= conversions =================
__global__ void halve_w3_kernel(const float* __restrict__ wk, const float* __restrict__ wi,
                                const float* __restrict__ wra,
                                __half* __restrict__ ok, __half* __restrict__ oi,
                                __half* __restrict__ ora)
{
    int i = blockIdx.x * 256 + threadIdx.x;
    if (i < 262144) ok[i] = __float2half_rn(wk[i]);
    else if (i < 786432) { int j = i - 262144; oi[j] = __float2half_rn(wi[j]); }
    else { int j = i - 786432; ora[j] = __float2half_rn(wra[j]); }
}

__global__ void transpose_half_k(const float* __restrict__ k, __half* __restrict__ kT)
{
    __shared__ float tile[32][33];
    int b  = blockIdx.z;
    int p0 = blockIdx.x * 32;
    int c0 = blockIdx.y * 32;
    int tx = threadIdx.x, ty = threadIdx.y;
    #pragma unroll
    for (int j = 0; j < 32; j += 8) {
        int c = c0 + ty + j, p = p0 + tx;
        if (p < PIX) tile[ty + j][tx] = k[((size_t)b * DIM + c) * PIX + p];
    }
    __syncthreads();
    #pragma unroll
    for (int j = 0; j < 32; j += 8) {
        int p = p0 + ty + j, c = c0 + tx;
        if (p < PIX)
            kT[((size_t)b * PIX + p) * 512 + c] = __float2half_rn(tile[tx][ty + j]);
    }
}

// ---------------- reduction helpers ----------------
template<int NW>
__device__ __forceinline__ float blkSum(float v, float* red) {
    #pragma unroll
    for (int o = 16; o > 0; o >>= 1) v += __shfl_xor_sync(0xffffffffu, v, o);
    __syncthreads();
    if ((threadIdx.x & 31) == 0) red[threadIdx.x >> 5] = v;
    __syncthreads();
    float s = 0.f;
    #pragma unroll
    for (int i = 0; i < NW; i++) s += red[i];
    return s;
}

// ---------------- ControlUnit tail: warp-per-l ----------------
__global__ void __launch_bounds__(512) control_kernel(
    const float* __restrict__ cq, const float* __restrict__ cw,
    const int* __restrict__ mask, const float* __restrict__ Wca,
    const float* __restrict__ bca,
    float* __restrict__ cv_out, float* __restrict__ cnew)
{
    int b = blockIdx.x, tid = threadIdx.x;
    int w = tid >> 5, lane = tid & 31;
    __shared__ float u[DIM];
    __shared__ float s[LW];
    const float* cwb = cw + (size_t)b * LW * DIM;
    u[tid] = cq[(size_t)b * DIM + tid] * Wca[tid];
    __syncthreads();
    #pragma unroll
    for (int li = 0; li < 2; li++) {
        int l = w * 2 + li;
        const float* row = cwb + (size_t)l * DIM;
        float p = 0.f;
        #pragma unroll
        for (int j = 0; j < 16; j++) p = fmaf(u[lane + j * 32], row[lane + j * 32], p);
        #pragma unroll
        for (int o = 16; o > 0; o >>= 1) p += __shfl_xor_sync(0xffffffffu, p, o);
        if (lane == 0) s[l] = (mask[b * LW + l] > 0) ? (p + bca[0]) : -INFINITY;
    }
    __syncthreads();
    if (tid == 0) {
        float mx = -INFINITY;
        for (int l = 0; l < LW; l++) mx = fmaxf(mx, s[l]);
        float sm = 0.f;
        for (int l = 0; l < LW; l++) { float e = __expf(s[l] - mx); s[l] = e; sm += e; }
        float inv = 1.f / sm;
        for (int l = 0; l < LW; l++) { s[l] *= inv; cv_out[b * LW + l] = s[l]; }
    }
    __syncthreads();
    float a = 0.f;
    #pragma unroll
    for (int l = 0; l < LW; l++) a = fmaf(s[l], cwb[(size_t)l * DIM + tid], a);
    cnew[(size_t)b * DIM + tid] = a;
}

// ---------------- softmax over channels: warp-per-pixel, 28-pixel staging ----------
#define SMRV_TILE_STRIDE 517
#define SMRV_SMEM (28*SMRV_TILE_STRIDE*4)

__global__ void __launch_bounds__(512) softmax_rv_kernel(
    const __half* __restrict__ ra, const __half* __restrict__ kT,
    float* __restrict__ rv_out, float* __restrict__ r_out)
{
    extern __shared__ float tile[];
    __shared__ float rsum[DIM];
    const int b = blockIdx.x, tid = threadIdx.x;
    const int w = tid >> 5, lane = tid & 31;
    const __half* rab = ra + (size_t)b * PIX * 512;
    const __half* kb = kT + (size_t)b * PIX * 512;
    float* rvb = rv_out + (size_t)b * DIM * PIX;

    if (tid < DIM) rsum[tid] = 0.f;
    float racc[16];
    #pragma unroll
    for (int j = 0; j < 16; j++) racc[j] = 0.f;
    __syncthreads();

    for (int pp = 0; pp < 7; pp++) {
        if (w < 14) {
            #pragma unroll
            for (int half = 0; half < 2; half++) {
                const int i = half * 14 + w;
                const int p = pp * 28 + i;
                float x[16];
                #pragma unroll
                for (int q = 0; q < 4; q++) {
                    const size_t ridx = (size_t)p * 512 + q * 128 + lane * 4;
                    __half2 r0 = *reinterpret_cast<const __half2*>(rab + ridx);
                    __half2 r1 = *reinterpret_cast<const __half2*>(rab + ridx + 2);
                    x[q * 4 + 0] = __half2float(r0.x); x[q * 4 + 1] = __half2float(r0.y);
                    x[q * 4 + 2] = __half2float(r1.x); x[q * 4 + 3] = __half2float(r1.y);
                }
                float mx = x[0];
                #pragma unroll
                for (int j = 1; j < 16; j++) mx = fmaxf(mx, x[j]);
                #pragma unroll
                for (int o = 16; o > 0; o >>= 1) mx = fmaxf(mx, __shfl_xor_sync(0xffffffffu, mx, o));
                float sm = 0.f;
                #pragma unroll
                for (int j = 0; j < 16; j++) { x[j] = __expf(x[j] - mx); sm += x[j]; }
                #pragma unroll
                for (int o = 16; o > 0; o >>= 1) sm += __shfl_xor_sync(0xffffffffu, sm, o);
                const float inv = 1.f / sm;
                #pragma unroll
                for (int q = 0; q < 4; q++) {
                    float rv0 = x[q * 4 + 0] * inv, rv1 = x[q * 4 + 1] * inv;
                    float rv2 = x[q * 4 + 2] * inv, rv3 = x[q * 4 + 3] * inv;
                    float* tr = &tile[i * SMRV_TILE_STRIDE + q * 128 + lane * 4];
                    tr[0] = rv0; tr[1] = rv1; tr[2] = rv2; tr[3] = rv3;
                    const size_t kidx = (size_t)p * 512 + q * 128 + lane * 4;
                    __half2 kh0 = *reinterpret_cast<const __half2*>(kb + kidx);
                    __half2 kh1 = *reinterpret_cast<const __half2*>(kb + kidx + 2);
                    racc[q * 4 + 0] = fmaf(rv0, __half2float(kh0.x), racc[q * 4 + 0]);
                    racc[q * 4 + 1] = fmaf(rv1, __half2float(kh0.y), racc[q * 4 + 1]);
                    racc[q * 4 + 2] = fmaf(rv2, __half2float(kh1.x), racc[q * 4 + 2]);
                    racc[q * 4 + 3] = fmaf(rv3, __half2float(kh1.y), racc[q * 4 + 3]);
                }
            }
        }
        __syncthreads();
        #pragma unroll 1
        for (int cc = 0; cc < 32; cc++) {
            int c = w * 32 + cc;
            if (lane < 28) rvb[(size_t)c * PIX + pp * 28 + lane] = tile[lane * SMRV_TILE_STRIDE + c];
        }
        __syncthreads();
    }

    #pragma unroll
    for (int q = 0; q < 4; q++)
        #pragma unroll
        for (int j = 0; j < 4; j++)
            atomicAdd(&rsum[q * 128 + lane * 4 + j], racc[q * 4 + j]);
    __syncthreads();
    if (tid < DIM) r_out[(size_t)b * DIM + tid] = rsum[tid];
}

// ---------------- gate, sa softmax over T, m_sa ----------------
__global__ void gate_sa_kernel(const float* __restrict__ cnew, const float* __restrict__ Wc,
                               const float* __restrict__ bc,   const float* __restrict__ cs,
                               const float* __restrict__ Wsa,  const float* __restrict__ bsa,
                               const float* __restrict__ ms,
                               float* __restrict__ gate_out, float* __restrict__ msa_out)
{
    int b = blockIdx.x, tid = threadIdx.x;
    __shared__ float red[8];
    __shared__ float sa[TT];
    __shared__ float gsh;
    float p = 0.f;
    for (int d = tid; d < DIM; d += 256) p += cnew[(size_t)b * DIM + d] * Wc[d];
    float tot = blkSum<8>(p, red);
    if (tid == 0) gsh = 1.f / (1.f + __expf(-(tot + bc[0])));
    __syncthreads();
    float gate = gsh;
    for (int t8 = 0; t8 < TT; t8++) {
        float qv = 0.f;
        const float* csrow = cs + ((size_t)t8 * BATCH + b) * DIM;
        for (int d = tid; d < DIM; d += 256) qv += csrow[d] * Wsa[d];
        float qt = blkSum<8>(qv, red);
        if (tid == 0) sa[t8] = gate * qt + bsa[0];
    }
    __syncthreads();
    if (tid == 0) {
        float mx = -INFINITY;
        for (int i = 0; i < TT; i++) mx = fmaxf(mx, sa[i]);
        float sm = 0.f;
        for (int i = 0; i < TT; i++) { float e = __expf(sa[i] - mx); sa[i] = e; sm += e; }
        float inv = 1.f / sm;
        for (int i = 0; i < TT; i++) sa[i] *= inv;
    }
    __syncthreads();
    for (int d = tid; d < DIM; d += 256) {
        float a = 0.f;
        #pragma unroll
        for (int i = 0; i < TT; i++)
            a = fmaf(sa[i], ms[((size_t)i * BATCH + b) * DIM + d], a);
        msa_out[(size_t)b * DIM + d] = a;
    }
    if (tid == 0) gate_out[b] = gate;
}

// ---------------- launch ----------------
extern "C" void kernel_launch(void* const* d_in, const int* in_sizes, int n_in,
                              void* d_out, int out_size)
{
    const float* c    = (const float*)d_in[0];
    const float* m    = (const float*)d_in[1];
    const float* k    = (const float*)d_in[2];
    const float* q    = (const float*)d_in[3];
    const float* cw   = (const float*)d_in[4];
    const int*   mask = (const int*)  d_in[5];
    const float* cs   = (const float*)d_in[6];
    const float* ms   = (const float*)d_in[7];
    const float* Wcq  = (const float*)d_in[8];
    const float* bcq  = (const float*)d_in[9];
    const float* Wca  = (const float*)d_in[10];
    const float* bca  = (const float*)d_in[11];
    const float* Wm_r = (const float*)d_in[12];
    const float* bm_r = (const float*)d_in[13];
    const float* Wk   = (const float*)d_in[14];
    const float* bk   = (const float*)d_in[15];
    const float* WI   = (const float*)d_in[16];
    const float* bI   = (const float*)d_in[17];
    const float* Wra  = (const float*)d_in[18];
    const float* bra  = (const float*)d_in[19];
    const float* Wm_w = (const float*)d_in[20];
    const float* bm_w = (const float*)d_in[21];
    const float* Wsa  = (const float*)d_in[22];
    const float* bsa  = (const float*)d_in[23];
    const float* Wm2  = (const float*)d_in[24];
    const float* bm2  = (const float*)d_in[25];
    const float* Wc   = (const float*)d_in[26];
    const float* bc   = (const float*)d_in[27];
    const float* Ws   = (const float*)d_in[28];

    float* out      = (float*)d_out;
    float* out_cnew = out;
    float* out_mnew = out + 131072;
    float* out_cv   = out + 262144;
    float* out_rv   = out + 270336;

    __half *p_kT, *p_I2, *p_J2, *p_ra, *p_Wk2, *p_WI2, *p_Wra2;
    float *p_cq, *p_mI, *p_r, *p_msa, *p_tmp, *p_gate, *p_part, *p_part2;
    cudaGetSymbolAddress((void**)&p_kT,   g_kT);
    cudaGetSymbolAddress((void**)&p_I2,   g_I2);
    cudaGetSymbolAddress((void**)&p_J2,   g_J2);
    cudaGetSymbolAddress((void**)&p_ra,   g_ra);
    cudaGetSymbolAddress((void**)&p_Wk2,  g_Wk2);
    cudaGetSymbolAddress((void**)&p_WI2,  g_WI2);
    cudaGetSymbolAddress((void**)&p_Wra2, g_Wra2);
    cudaGetSymbolAddress((void**)&p_cq,   g_cq);
    cudaGetSymbolAddress((void**)&p_mI,   g_mI);
    cudaGetSymbolAddress((void**)&p_r,    g_r);
    cudaGetSymbolAddress((void**)&p_msa,  g_msa);
    cudaGetSymbolAddress((void**)&p_tmp,  g_tmp);
    cudaGetSymbolAddress((void**)&p_gate, g_gate);
    cudaGetSymbolAddress((void**)&p_part, g_part);
    cudaGetSymbolAddress((void**)&p_part2,g_part2);

    cudaFuncSetAttribute((const void*)mma_gemm<512,  false, 0>, cudaFuncAttributeMaxDynamicSharedMemorySize, MG_SMEM);
    cudaFuncSetAttribute((const void*)mma_gemm<1024, true,  0>, cudaFuncAttributeMaxDynamicSharedMemorySize, MG_SMEM);
    cudaFuncSetAttribute((const void*)mma_gemm<512,  false, 1>, cudaFuncAttributeMaxDynamicSharedMemorySize, MG_SMEM);
    cudaFuncSetAttribute(softmax_rv_kernel, cudaFuncAttributeMaxDynamicSharedMemorySize, SMRV_SMEM);

    // ================== two-stream DAG (R14 spine) ==================
    cudaStream_t s2 = g_s2;

    // s0: transpose first
    transpose_half_k<<<dim3(7, 16, BATCH), dim3(32, 8)>>>(k, p_kT);

    cudaEventRecord(g_evFork, 0);
    cudaStreamWaitEvent(s2, g_evFork, 0);

    // s2 chain (hidden under big GEMMs)
    halve_w3_kernel<<<4096, 256, 0, s2>>>(Wk, WI, Wra, p_Wk2, p_WI2, p_Wra2);
    gemm_small<512, false><<<dim3(16, 8), 256, 0, s2>>>(m, nullptr, Wm_r, bm_r, p_mI);
    cudaEventRecord(g_evA, s2);
    gemm_small<1024, true><<<dim3(16, 8), 256, 0, s2>>>(c, q, Wcq, bcq, p_cq);
    control_kernel<<<BATCH, 512, 0, s2>>>(p_cq, cw, mask, Wca, bca, out_cv, out_cnew);
    cudaEventRecord(g_evB, s2);
    // m_prev m-half (K 512..1023 of concat; independent of r) -> parts 2,3
    gemm_part<<<dim3(16, 8, 2), 256, 0, s2>>>(m, 512, Wm_w, 1024, 512, p_part + 2 * BD);
    cudaEventRecord(g_evG, s2);
    gate_sa_kernel<<<BATCH, 256, 0, s2>>>(out_cnew, Wc, bc, cs, Wsa, bsa, ms, p_gate, p_msa);
    gemm_small<512, false><<<dim3(16, 8), 256, 0, s2>>>(p_msa, nullptr, Ws, nullptr, p_tmp);
    cudaEventRecord(g_evC, s2);

    // s0 chain
    cudaStreamWaitEvent(0, g_evA, 0);
    mma_gemm<512, false, 0><<<dim3(4, 392), 256, MG_SMEM>>>(
        p_kT, nullptr, p_Wk2, bk, p_mI, p_I2);
    cudaStreamWaitEvent(0, g_evB, 0);
    mma_gemm<1024, true, 0><<<dim3(4, 392), 256, MG_SMEM>>>(
        p_I2, p_kT, p_WI2, bI, out_cnew, p_J2);
    mma_gemm<512, false, 1><<<dim3(4, 392), 256, MG_SMEM>>>(
        p_J2, nullptr, p_Wra2, bra, nullptr, p_ra);
    softmax_rv_kernel<<<BATCH, 512, SMRV_SMEM>>>(p_ra, p_kT, out_rv, p_r);
    // m_prev r-half (K 0..511) -> parts 0,1
    gemm_part<<<dim3(16, 8, 2), 256>>>(p_r, 512, Wm_w, 1024, 0, p_part);
    cudaStreamWaitEvent(0, g_evG, 0);
    // m_ = (bm_w + Σparts) @ Wm2^T, split-K fused (2 chunks)
    gemm_part_fused<<<dim3(16, 8, 2), 256>>>(p_part, bm_w, Wm2, 512, p_part2);
    cudaStreamWaitEvent(0, g_evC, 0);
    // m_new = g*m + (1-g)*((bm2 + p0 + p1) + tmp)
    final2_kernel<<<BD / 256, 256>>>(p_part2, bm2, m, p_tmp, p_gate, out_mnew);
}